// round 14
// baseline (speedup 1.0000x reference)
#include <cuda_runtime.h>
#include <cuda_bf16.h>
#include <cstdint>

namespace {
constexpr int Bn = 32;
constexpr int Tn = 1024;
constexpr int M  = Bn * 1024;

constexpr int Lc = 8;
constexpr int Cc = Tn / Lc;         // 128

constexpr int SZ  = 512 * 512;      // fp32 elements per matrix
constexpr int SZW = 256 * 512;      // packed bf16x2 words per matrix
constexpr int WST = 20;             // smem row stride in words
constexpr int BUFW = 7680;          // Ah 2560 | Al 2560 | Bh 1280 | Bl 1280
constexpr int SMEM_BYTES = 2 * BUFW * 4;   // 61440
}

// ---------------------------------------------------------------------------
// Static device scratch
// ---------------------------------------------------------------------------
__device__ float    g_Rf[8 * SZ];       // R^1..R^8 fp32
__device__ uint32_t g_Rh[8 * SZW];      // R^1..R^8 B-style packed hi
__device__ uint32_t g_Rl[8 * SZW];
__device__ float    g_Sf[6 * SZ];       // S^2,S^4,S^8,S^16,S^32,S^64 (S = R^8)
__device__ uint32_t g_Sh[6 * SZW];
__device__ uint32_t g_Sl[6 * SZW];
__device__ uint32_t g_Wh[SZW];
__device__ uint32_t g_Wl[SZW];
__device__ float    g_V0[Cc * Bn * 512];   // 4096 x 512
__device__ float    g_V1[Cc * Bn * 512];

// ---------------------------------------------------------------------------
// helpers
// ---------------------------------------------------------------------------
__device__ __forceinline__ uint32_t packbf(float a, float b) {
    uint32_t r;  // low half = a, high half = b
    asm("cvt.rn.bf16x2.f32 %0, %1, %2;" : "=r"(r) : "f"(b), "f"(a));
    return r;
}
__device__ __forceinline__ float lo_f(uint32_t p) { return __uint_as_float(p << 16); }
__device__ __forceinline__ float hi_f(uint32_t p) { return __uint_as_float(p & 0xFFFF0000u); }

__device__ __forceinline__ void mma16816(float* c, const uint32_t* a,
                                         uint32_t b0, uint32_t b1) {
    asm volatile(
        "mma.sync.aligned.m16n8k16.row.col.f32.bf16.bf16.f32 "
        "{%0,%1,%2,%3}, {%4,%5,%6,%7}, {%8,%9}, {%0,%1,%2,%3};"
        : "+f"(c[0]), "+f"(c[1]), "+f"(c[2]), "+f"(c[3])
        : "r"(a[0]), "r"(a[1]), "r"(a[2]), "r"(a[3]), "r"(b0), "r"(b1));
}

__device__ __forceinline__ void ldsm4(uint32_t& r0, uint32_t& r1,
                                      uint32_t& r2, uint32_t& r3, uint32_t addr) {
    asm volatile(
        "ldmatrix.sync.aligned.m8n8.x4.shared.b16 {%0,%1,%2,%3}, [%4];"
        : "=r"(r0), "=r"(r1), "=r"(r2), "=r"(r3) : "r"(addr));
}

// row c of V lives in: V0 if c==0, else buffer (floor(log2 c)+1)&1
__device__ __forceinline__ const float* v_final_base(const float* V0,
                                                     const float* V1, int c) {
    if (c <= 0) return V0;
    const int b = ((31 - __clz(c)) + 1) & 1;
    return b ? V1 : V0;
}

// ---------------------------------------------------------------------------
// Double-buffered HMMA core (fp32 A converted in-kernel, pre-packed B,
// ldmatrix fragment loads).  Unchanged from round 13.
// ---------------------------------------------------------------------------
__device__ __forceinline__ void hmma_core_bb(const float* __restrict__ arow,
                                             const uint32_t* __restrict__ bh,
                                             const uint32_t* __restrict__ bl,
                                             float acc[2][4][4])
{
    extern __shared__ uint32_t sw[];
    const uint32_t sb = (uint32_t)__cvta_generic_to_shared(sw);
    const int tid  = threadIdx.x;
    const int lane = tid & 31, wid = tid >> 5;
    const int mo = (wid >> 1) * 32, no = (wid & 1) * 32;

    const int sar = tid >> 1;
    const int saw = (tid & 1) * 8;
    const int sbw = (tid >> 6) * 4;

    const int aoffw = (lane & 15) * WST + (lane >> 4) * 4;
    const int jj = lane >> 3, iL = lane & 7;
    const int boffw = ((jj >> 1) * 8 + iL) * WST + (jj & 1) * 4;

    float af[16];
    uint32_t bhw[4], blw[4];

    auto LOAD = [&](int kc) {
        const float* ap = arow + kc * 32;
        float4 v;
        v = *(const float4*)(ap + 0);  af[0] = v.x;  af[1] = v.y;  af[2] = v.z;  af[3] = v.w;
        v = *(const float4*)(ap + 4);  af[4] = v.x;  af[5] = v.y;  af[6] = v.z;  af[7] = v.w;
        v = *(const float4*)(ap + 8);  af[8] = v.x;  af[9] = v.y;  af[10] = v.z; af[11] = v.w;
        v = *(const float4*)(ap + 12); af[12] = v.x; af[13] = v.y; af[14] = v.z; af[15] = v.w;
        const int off = (kc * 16 + sbw) * 512;
        bhw[0] = bh[off];        bhw[1] = bh[off + 512];
        bhw[2] = bh[off + 1024]; bhw[3] = bh[off + 1536];
        blw[0] = bl[off];        blw[1] = bl[off + 512];
        blw[2] = bl[off + 1024]; blw[3] = bl[off + 1536];
    };

    auto STORE = [&](int bi) {
        uint32_t h[8], l[8];
#pragma unroll
        for (int j = 0; j < 8; j++) {
            h[j] = packbf(af[2 * j], af[2 * j + 1]);
            l[j] = packbf(af[2 * j] - lo_f(h[j]), af[2 * j + 1] - hi_f(h[j]));
        }
        uint32_t* pA = sw + bi * BUFW + sar * WST + saw;
        *(uint4*)pA        = make_uint4(h[0], h[1], h[2], h[3]);
        *(uint4*)(pA + 4)  = make_uint4(h[4], h[5], h[6], h[7]);
        uint32_t* pAl = pA + 2560;
        *(uint4*)pAl       = make_uint4(l[0], l[1], l[2], l[3]);
        *(uint4*)(pAl + 4) = make_uint4(l[4], l[5], l[6], l[7]);
        uint32_t* pB = sw + bi * BUFW + 5120 + (tid & 63) * WST + sbw;
        *(uint4*)pB          = make_uint4(bhw[0], bhw[1], bhw[2], bhw[3]);
        *(uint4*)(pB + 1280) = make_uint4(blw[0], blw[1], blw[2], blw[3]);
    };

    auto COMPUTE = [&](int bi) {
        const uint32_t base = sb + (uint32_t)(bi * BUFW) * 4u;
#pragma unroll
        for (int s = 0; s < 2; s++) {
            const int ws = s * 8;
            uint32_t aH[2][4], aL[2][4];
#pragma unroll
            for (int mf = 0; mf < 2; mf++) {
                const uint32_t wa = base + (uint32_t)(((mo + mf * 16) * WST + ws + aoffw) * 4);
                ldsm4(aH[mf][0], aH[mf][1], aH[mf][2], aH[mf][3], wa);
                ldsm4(aL[mf][0], aL[mf][1], aL[mf][2], aL[mf][3], wa + 2560u * 4u);
            }
#pragma unroll
            for (int p = 0; p < 2; p++) {
                const uint32_t wb = base +
                    (uint32_t)((5120 + (no + p * 16) * WST + ws + boffw) * 4);
                uint32_t h0, h1, h2, h3, l0, l1, l2, l3;
                ldsm4(h0, h1, h2, h3, wb);
                ldsm4(l0, l1, l2, l3, wb + 1280u * 4u);
#pragma unroll
                for (int mf = 0; mf < 2; mf++) {
                    mma16816(acc[mf][2 * p],     aH[mf], h0, h1);
                    mma16816(acc[mf][2 * p],     aH[mf], l0, l1);
                    mma16816(acc[mf][2 * p],     aL[mf], h0, h1);
                    mma16816(acc[mf][2 * p + 1], aH[mf], h2, h3);
                    mma16816(acc[mf][2 * p + 1], aH[mf], l2, l3);
                    mma16816(acc[mf][2 * p + 1], aL[mf], h2, h3);
                }
            }
        }
    };

    LOAD(0); STORE(0); __syncthreads();
    int cur = 0;
    for (int kc = 0; kc < 16; kc++) {
        if (kc < 15) LOAD(kc + 1);
        COMPUTE(cur);
        if (kc < 15) { STORE(cur ^ 1); __syncthreads(); cur ^= 1; }
    }
}

// ladder epilogue: fp32 C + B-style packed (row-pair shuffle)
__device__ __forceinline__ void ladder_epilogue(
    const float acc[2][4][4], int mrow, int bn,
    float* __restrict__ Cz, uint32_t* __restrict__ Dh, uint32_t* __restrict__ Dl)
{
    const int tid = threadIdx.x;
    const int lane = tid & 31, wid = tid >> 5;
    const int g = lane >> 2, qi = lane & 3;
    const int mo = (wid >> 1) * 32, no = (wid & 1) * 32;
#pragma unroll
    for (int mf = 0; mf < 2; mf++)
#pragma unroll
        for (int f = 0; f < 4; f++) {
            const int r0  = mrow + mo + mf * 16 + g;
            const int col = bn + no + f * 8 + 2 * qi;
            *(float2*)(Cz + (size_t)r0 * 512 + col) =
                make_float2(acc[mf][f][0], acc[mf][f][1]);
            *(float2*)(Cz + (size_t)(r0 + 8) * 512 + col) =
                make_float2(acc[mf][f][2], acc[mf][f][3]);

            float pc0 = __shfl_sync(0xffffffffu, acc[mf][f][0], (lane + 4) & 31);
            float pc1 = __shfl_sync(0xffffffffu, acc[mf][f][1], (lane + 4) & 31);
            float pc2 = __shfl_sync(0xffffffffu, acc[mf][f][2], (lane + 4) & 31);
            float pc3 = __shfl_sync(0xffffffffu, acc[mf][f][3], (lane + 4) & 31);
            if ((g & 1) == 0) {
                const int w0 = r0 >> 1;
                const int w1 = (r0 + 8) >> 1;
                uint32_t h0 = packbf(acc[mf][f][0], pc0);
                Dh[(size_t)w0 * 512 + col] = h0;
                Dl[(size_t)w0 * 512 + col] =
                    packbf(acc[mf][f][0] - lo_f(h0), pc0 - hi_f(h0));
                uint32_t h1 = packbf(acc[mf][f][1], pc1);
                Dh[(size_t)w0 * 512 + col + 1] = h1;
                Dl[(size_t)w0 * 512 + col + 1] =
                    packbf(acc[mf][f][1] - lo_f(h1), pc1 - hi_f(h1));
                uint32_t h2 = packbf(acc[mf][f][2], pc2);
                Dh[(size_t)w1 * 512 + col] = h2;
                Dl[(size_t)w1 * 512 + col] =
                    packbf(acc[mf][f][2] - lo_f(h2), pc2 - hi_f(h2));
                uint32_t h3 = packbf(acc[mf][f][3], pc3);
                Dh[(size_t)w1 * 512 + col + 1] = h3;
                Dl[(size_t)w1 * 512 + col + 1] =
                    packbf(acc[mf][f][3] - lo_f(h3), pc3 - hi_f(h3));
            }
        }
}

// ---------------------------------------------------------------------------
// generic C = A @ B (fp32 out).  grid (n/64, m/128).  Used for XW.
// ---------------------------------------------------------------------------
__global__ __launch_bounds__(256, 2) void hmma_gemm_bb(
    const float* __restrict__ A, const uint32_t* __restrict__ Bh,
    const uint32_t* __restrict__ Bl, float* __restrict__ C)
{
    const int bn = blockIdx.x * 64;
    const int bm = blockIdx.y * 128;
    const int tid = threadIdx.x;
    const float* arow = A + (size_t)(bm + (tid >> 1)) * 512 + (tid & 1) * 16;
    float acc[2][4][4] = {};
    hmma_core_bb(arow, Bh + bn + (tid & 63), Bl + bn + (tid & 63), acc);

    const int lane = tid & 31, wid = tid >> 5;
    const int g = lane >> 2, qi = lane & 3;
    const int mo = (wid >> 1) * 32, no = (wid & 1) * 32;
#pragma unroll
    for (int mf = 0; mf < 2; mf++)
#pragma unroll
        for (int f = 0; f < 4; f++) {
            const int r0  = bm + mo + mf * 16 + g;
            const int col = bn + no + f * 8 + 2 * qi;
            *(float2*)(C + (size_t)r0 * 512 + col) =
                make_float2(acc[mf][f][0], acc[mf][f][1]);
            *(float2*)(C + (size_t)(r0 + 8) * 512 + col) =
                make_float2(acc[mf][f][2], acc[mf][f][3]);
        }
}

// ---------------------------------------------------------------------------
// Mega pass1 step: y < 32 -> pass1 tile; y >= 32 (4 blocks) -> one ladder
// matrix product (mt = 4 always).  t == Lc-1 also seeds V0.
// ---------------------------------------------------------------------------
__global__ __launch_bounds__(256, 2) void mega_step_kernel(
    float* __restrict__ O, int t, float* __restrict__ V0,
    const float* __restrict__ LA,
    const uint32_t* __restrict__ LBh, const uint32_t* __restrict__ LBl,
    float* __restrict__ LCf, uint32_t* __restrict__ LCh, uint32_t* __restrict__ LCl)
{
    const int bn  = blockIdx.x * 64;
    const int tid = threadIdx.x;

    if (blockIdx.y < 32) {
        const int bm = blockIdx.y * 128;
        const int srow = bm + (tid >> 1);
        const float* arow = O + ((size_t)(srow & 31) * Tn + (size_t)(srow >> 5) * Lc + (t - 1)) * 512
                            + (tid & 1) * 16;
        float acc[2][4][4] = {};
        hmma_core_bb(arow, g_Rh + bn + (tid & 63), g_Rl + bn + (tid & 63), acc);

        const int lane = tid & 31, wid = tid >> 5;
        const int g = lane >> 2, qi = lane & 3;
        const int mo = (wid >> 1) * 32, no = (wid & 1) * 32;
#pragma unroll
        for (int mf = 0; mf < 2; mf++)
#pragma unroll
            for (int f = 0; f < 4; f++) {
                const int col = bn + no + f * 8 + 2 * qi;
#pragma unroll
                for (int h = 0; h < 2; h++) {
                    const int r = bm + mo + mf * 16 + g + h * 8;
                    float* op = O + ((size_t)(r & 31) * Tn + (size_t)(r >> 5) * Lc + t) * 512 + col;
                    float2 e = *(float2*)op;
                    e.x += acc[mf][f][2 * h];
                    e.y += acc[mf][f][2 * h + 1];
                    *(float2*)op = e;
                    if (t == Lc - 1)
                        *(float2*)(V0 + (size_t)r * 512 + col) = e;
                }
            }
    } else {
        const int mrow = (blockIdx.y - 32) * 128;
        const float* arow = LA + (size_t)(mrow + (tid >> 1)) * 512 + (tid & 1) * 16;
        float acc[2][4][4] = {};
        hmma_core_bb(arow, LBh + bn + (tid & 63), LBl + bn + (tid & 63), acc);
        ladder_epilogue(acc, mrow, bn, LCf, LCh, LCl);
    }
}

// ---------------------------------------------------------------------------
// Scan step i (d = 2^i): rows with c >= d only.  grid (8, yscan [+4 ladder]).
//   out[c] = cur[c] + src[c-d] @ S^d,  c >= d
// cur (addend) lives in buffer (i&1); out is buffer ((i+1)&1); sources with
// s >= d live in buffer (i&1), finalized sources in v_final_base(s).
// ---------------------------------------------------------------------------
__global__ __launch_bounds__(256, 2) void hmma_scan_step(
    float* __restrict__ V0, float* __restrict__ V1, int i, int yscan,
    const uint32_t* __restrict__ Sh, const uint32_t* __restrict__ Sl,
    const float* __restrict__ LA,
    const uint32_t* __restrict__ LBh, const uint32_t* __restrict__ LBl,
    float* __restrict__ LCf, uint32_t* __restrict__ LCh, uint32_t* __restrict__ LCl)
{
    const int bn  = blockIdx.x * 64;
    const int tid = threadIdx.x;
    const int d   = 1 << i;

    if ((int)blockIdx.y < yscan) {
        const float* Vcur = (i & 1) ? V1 : V0;
        float* Vout = (i & 1) ? V0 : V1;
        const int bm = (blockIdx.y + (32 - yscan)) * 128;

        // A staging: source row for target row tr = bm + (tid>>1)
        const int tr = bm + (tid >> 1);
        const int ct = tr >> 5;
        const int s  = ct - d;
        const int sr = (s >= 0) ? (s * 32 + (tr & 31)) : tr;   // dummy if skip row
        const float* sbase = (s >= d) ? Vcur : v_final_base(V0, V1, s);
        const float* arow = sbase + (size_t)sr * 512 + (tid & 1) * 16;

        float acc[2][4][4] = {};
        hmma_core_bb(arow, Sh + bn + (tid & 63), Sl + bn + (tid & 63), acc);

        const int lane = tid & 31, wid = tid >> 5;
        const int g = lane >> 2, qi = lane & 3;
        const int mo = (wid >> 1) * 32, no = (wid & 1) * 32;
#pragma unroll
        for (int mf = 0; mf < 2; mf++)
#pragma unroll
            for (int f = 0; f < 4; f++) {
                const int col = bn + no + f * 8 + 2 * qi;
#pragma unroll
                for (int h = 0; h < 2; h++) {
                    const int r = bm + mo + mf * 16 + g + h * 8;
                    if ((r >> 5) >= d) {
                        float2 e = *(const float2*)(Vcur + (size_t)r * 512 + col);
                        e.x += acc[mf][f][2 * h];
                        e.y += acc[mf][f][2 * h + 1];
                        *(float2*)(Vout + (size_t)r * 512 + col) = e;
                    }
                }
            }
    } else {
        const int mrow = (blockIdx.y - yscan) * 128;
        const float* arow = LA + (size_t)(mrow + (tid >> 1)) * 512 + (tid & 1) * 16;
        float acc[2][4][4] = {};
        hmma_core_bb(arow, LBh + bn + (tid & 63), LBl + bn + (tid & 63), acc);
        ladder_epilogue(acc, mrow, bn, LCf, LCh, LCl);
    }
}

// ---------------------------------------------------------------------------
// pass3: O[b, 8*(c+1)+t, :] += V[c] @ R^{t+1};  V[c] read from its final
// buffer.  grid (8, 32, 8: t)
// ---------------------------------------------------------------------------
__global__ __launch_bounds__(256, 2) void hmma_pass3_bb(
    float* __restrict__ O, const float* __restrict__ V0,
    const float* __restrict__ V1)
{
    const int t  = blockIdx.z;
    const int bn = blockIdx.x * 64;
    const int bm = blockIdx.y * 128;
    const int tid = threadIdx.x;
    const int vr = bm + (tid >> 1);
    const float* vb = v_final_base(V0, V1, vr >> 5);
    const float* arow = vb + (size_t)vr * 512 + (tid & 1) * 16;
    float acc[2][4][4] = {};
    hmma_core_bb(arow, g_Rh + (size_t)t * SZW + bn + (tid & 63),
                 g_Rl + (size_t)t * SZW + bn + (tid & 63), acc);

    const int lane = tid & 31, wid = tid >> 5;
    const int g = lane >> 2, qi = lane & 3;
    const int mo = (wid >> 1) * 32, no = (wid & 1) * 32;
#pragma unroll
    for (int mf = 0; mf < 2; mf++)
#pragma unroll
        for (int f = 0; f < 4; f++) {
            const int col = bn + no + f * 8 + 2 * qi;
#pragma unroll
            for (int h = 0; h < 2; h++) {
                const int r = bm + mo + mf * 16 + g + h * 8;
                const int cidx = r >> 5;       // = c-1
                if (cidx < Cc - 1) {
                    const int b = r & 31;
                    float* op = O + ((size_t)b * Tn + (size_t)(cidx + 1) * Lc + t) * 512 + col;
                    float2 e = *(float2*)op;
                    e.x += acc[mf][f][2 * h];
                    e.y += acc[mf][f][2 * h + 1];
                    *(float2*)op = e;
                }
            }
        }
}

// ---------------------------------------------------------------------------
// Merged prologue: pack W (blocks 0-511), pack R (512-1023), copy R->Rf
// (1024-1279).
// ---------------------------------------------------------------------------
__global__ void prologue_kernel(const float* __restrict__ w,
                                const float* __restrict__ r)
{
    const int bid = blockIdx.x;
    if (bid < 1024) {
        const bool isW = bid < 512;
        const float* src = isW ? w : r;
        uint32_t* dh = isW ? g_Wh : g_Rh;
        uint32_t* dl = isW ? g_Wl : g_Rl;
        const int i = (isW ? bid : bid - 512) * 256 + threadIdx.x;
        const int ww = i >> 9, n = i & 511;
        const float* s = src + (size_t)(2 * ww) * 512 + n;
        const float s0 = s[0], s1 = s[512];
        const uint32_t h = packbf(s0, s1);
        dh[i] = h;
        dl[i] = packbf(s0 - lo_f(h), s1 - hi_f(h));
    } else {
        const int i = (bid - 1024) * 256 + threadIdx.x;
        ((float4*)g_Rf)[i] = ((const float4*)r)[i];
    }
}

// ---------------------------------------------------------------------------
// Launch sequence
// ---------------------------------------------------------------------------
extern "C" void kernel_launch(void* const* d_in, const int* in_sizes, int n_in,
                              void* d_out, int out_size)
{
    const float* x = (const float*)d_in[0];
    const float* w = (const float*)d_in[1];
    const float* r = (const float*)d_in[2];
    float* o = (float*)d_out;
    (void)in_sizes; (void)n_in; (void)out_size;

    float *Rf, *Sf, *V0, *V1;
    uint32_t *Rh, *Rl, *Sh, *Sl, *Wh, *Wl;
    cudaGetSymbolAddress((void**)&Rf, g_Rf);
    cudaGetSymbolAddress((void**)&Rh, g_Rh);
    cudaGetSymbolAddress((void**)&Rl, g_Rl);
    cudaGetSymbolAddress((void**)&Sf, g_Sf);
    cudaGetSymbolAddress((void**)&Sh, g_Sh);
    cudaGetSymbolAddress((void**)&Sl, g_Sl);
    cudaGetSymbolAddress((void**)&Wh, g_Wh);
    cudaGetSymbolAddress((void**)&Wl, g_Wl);
    cudaGetSymbolAddress((void**)&V0, g_V0);
    cudaGetSymbolAddress((void**)&V1, g_V1);

    cudaFuncSetAttribute(hmma_gemm_bb,     cudaFuncAttributeMaxDynamicSharedMemorySize, SMEM_BYTES);
    cudaFuncSetAttribute(mega_step_kernel, cudaFuncAttributeMaxDynamicSharedMemorySize, SMEM_BYTES);
    cudaFuncSetAttribute(hmma_scan_step,   cudaFuncAttributeMaxDynamicSharedMemorySize, SMEM_BYTES);
    cudaFuncSetAttribute(hmma_pass3_bb,    cudaFuncAttributeMaxDynamicSharedMemorySize, SMEM_BYTES);

    // Prologue (one kernel): pack W, pack R, seed Rf with R^1.
    prologue_kernel<<<1280, 256>>>(w, r);

    // Phase A: O = X @ W
    hmma_gemm_bb<<<dim3(8, M / 128), 256, SMEM_BYTES>>>(x, Wh, Wl, o);

    // Ladder: ONE matrix product per step slot (4 extra y-blocks -> grid 288).
    // pass1 slots t=1..7 produce R^2..R^8; scan slots i=0..5 produce S^2..S^64.
    struct Lad { const float* A; const uint32_t *Bh, *Bl; float* Cf; uint32_t *Ch, *Cl; };
    Lad lad1[8];
    lad1[1] = {Rf,          Rh,           Rl,           Rf + (size_t)1 * SZ, Rh + 1 * SZW, Rl + 1 * SZW};  // R^2 = R@R
    lad1[2] = {Rf,          Rh + 1 * SZW, Rl + 1 * SZW, Rf + (size_t)2 * SZ, Rh + 2 * SZW, Rl + 2 * SZW};  // R^3 = R@R^2
    lad1[3] = {Rf + 1 * SZ, Rh + 1 * SZW, Rl + 1 * SZW, Rf + (size_t)3 * SZ, Rh + 3 * SZW, Rl + 3 * SZW};  // R^4 = R^2@R^2
    lad1[4] = {Rf,          Rh + 3 * SZW, Rl + 3 * SZW, Rf + (size_t)4 * SZ, Rh + 4 * SZW, Rl + 4 * SZW};  // R^5 = R@R^4
    lad1[5] = {Rf + 1 * SZ, Rh + 3 * SZW, Rl + 3 * SZW, Rf + (size_t)5 * SZ, Rh + 5 * SZW, Rl + 5 * SZW};  // R^6 = R^2@R^4
    lad1[6] = {Rf + 2 * SZ, Rh + 3 * SZW, Rl + 3 * SZW, Rf + (size_t)6 * SZ, Rh + 6 * SZW, Rl + 6 * SZW};  // R^7 = R^3@R^4
    lad1[7] = {Rf + 3 * SZ, Rh + 3 * SZW, Rl + 3 * SZW, Rf + (size_t)7 * SZ, Rh + 7 * SZW, Rl + 7 * SZW};  // R^8 = R^4@R^4

    // Phase C + B: 7 pass1 steps, each with one piggybacked ladder product
    for (int t = 1; t < Lc; t++) {
        const Lad& L = lad1[t];
        mega_step_kernel<<<dim3(8, 36), 256, SMEM_BYTES>>>(
            o, t, V0, L.A, L.Bh, L.Bl, L.Cf, L.Ch, L.Cl);
    }

    // Scan-slot ladder: S^2..S^64 (S = R^8), one per slot i=0..5.
    Lad lads[7];
    lads[0] = {Rf + 7 * SZ, Rh + 7 * SZW, Rl + 7 * SZW, Sf,                  Sh,           Sl};            // S^2
    lads[1] = {Sf,          Sh,           Sl,           Sf + (size_t)1 * SZ, Sh + 1 * SZW, Sl + 1 * SZW};  // S^4
    lads[2] = {Sf + 1 * SZ, Sh + 1 * SZW, Sl + 1 * SZW, Sf + (size_t)2 * SZ, Sh + 2 * SZW, Sl + 2 * SZW};  // S^8
    lads[3] = {Sf + 2 * SZ, Sh + 2 * SZW, Sl + 2 * SZW, Sf + (size_t)3 * SZ, Sh + 3 * SZW, Sl + 3 * SZW};  // S^16
    lads[4] = {Sf + 3 * SZ, Sh + 3 * SZW, Sl + 3 * SZW, Sf + (size_t)4 * SZ, Sh + 4 * SZW, Sl + 4 * SZW};  // S^32
    lads[5] = {Sf + 4 * SZ, Sh + 4 * SZW, Sl + 4 * SZW, Sf + (size_t)5 * SZ, Sh + 5 * SZW, Sl + 5 * SZW};  // S^64
    lads[6] = lads[5];  // unused (no ladder in last slot)

    // Phase D: carry scan, 7 steps; step i uses S^{2^i} (i=0 -> R^8),
    // processes only rows c >= d, writes buffer (i+1)&1.
    for (int i = 0; i < 7; i++) {
        const int d = 1 << i;
        const int yscan = 32 - ((d >= 4) ? d / 4 : 0);
        const uint32_t* Sph = (i == 0) ? (Rh + (size_t)7 * SZW) : (Sh + (size_t)(i - 1) * SZW);
        const uint32_t* Spl = (i == 0) ? (Rl + (size_t)7 * SZW) : (Sl + (size_t)(i - 1) * SZW);
        const int lext = (i < 6) ? 4 : 0;
        const Lad& L = lads[i];
        hmma_scan_step<<<dim3(8, yscan + lext), 256, SMEM_BYTES>>>(
            V0, V1, i, yscan, Sph, Spl, L.A, L.Bh, L.Bl, L.Cf, L.Ch, L.Cl);
    }

    // Phase E: batched correction (t = 0..7), per-row final-buffer select
    hmma_pass3_bb<<<dim3(8, 32, Lc), 256, SMEM_BYTES>>>(o, V0, V1);
}

// round 15
// speedup vs baseline: 1.5062x; 1.5062x over previous
#include <cuda_runtime.h>
#include <cuda_bf16.h>
#include <cstdint>

namespace {
constexpr int Bn = 32;
constexpr int Tn = 1024;
constexpr int M  = Bn * 1024;

constexpr int Lc = 8;
constexpr int Cc = Tn / Lc;         // 128

constexpr int SZ  = 512 * 512;      // fp32 elements per matrix
constexpr int SZW = 256 * 512;      // packed bf16x2 words per matrix
constexpr int WST = 20;             // smem row stride in words
constexpr int BUFW = 7680;          // Ah 2560 | Al 2560 | Bh 1280 | Bl 1280
constexpr int SMEM_BYTES = 2 * BUFW * 4;   // 61440
}

// ---------------------------------------------------------------------------
// Static device scratch
// ---------------------------------------------------------------------------
__device__ float    g_Rf[8 * SZ];       // R^1..R^8 fp32
__device__ uint32_t g_Rh[8 * SZW];      // R^1..R^8 B-style packed hi
__device__ uint32_t g_Rl[8 * SZW];
__device__ float    g_Sf[6 * SZ];       // S^2,S^4,S^8,S^16,S^32,S^64 (S = R^8)
__device__ uint32_t g_Sh[6 * SZW];
__device__ uint32_t g_Sl[6 * SZW];
__device__ uint32_t g_Wh[SZW];
__device__ uint32_t g_Wl[SZW];
__device__ float    g_V0[Cc * Bn * 512];   // 4096 x 512
__device__ float    g_V1[Cc * Bn * 512];

// ---------------------------------------------------------------------------
// helpers
// ---------------------------------------------------------------------------
__device__ __forceinline__ uint32_t packbf(float a, float b) {
    uint32_t r;  // low half = a, high half = b
    asm("cvt.rn.bf16x2.f32 %0, %1, %2;" : "=r"(r) : "f"(b), "f"(a));
    return r;
}
__device__ __forceinline__ float lo_f(uint32_t p) { return __uint_as_float(p << 16); }
__device__ __forceinline__ float hi_f(uint32_t p) { return __uint_as_float(p & 0xFFFF0000u); }

__device__ __forceinline__ void mma16816(float* c, const uint32_t* a,
                                         uint32_t b0, uint32_t b1) {
    asm volatile(
        "mma.sync.aligned.m16n8k16.row.col.f32.bf16.bf16.f32 "
        "{%0,%1,%2,%3}, {%4,%5,%6,%7}, {%8,%9}, {%0,%1,%2,%3};"
        : "+f"(c[0]), "+f"(c[1]), "+f"(c[2]), "+f"(c[3])
        : "r"(a[0]), "r"(a[1]), "r"(a[2]), "r"(a[3]), "r"(b0), "r"(b1));
}

__device__ __forceinline__ void ldsm4(uint32_t& r0, uint32_t& r1,
                                      uint32_t& r2, uint32_t& r3, uint32_t addr) {
    asm volatile(
        "ldmatrix.sync.aligned.m8n8.x4.shared.b16 {%0,%1,%2,%3}, [%4];"
        : "=r"(r0), "=r"(r1), "=r"(r2), "=r"(r3) : "r"(addr));
}

// ---------------------------------------------------------------------------
// Double-buffered HMMA core (fp32 A converted in-kernel, pre-packed B,
// ldmatrix fragment loads).  Identical to round 13.
// ---------------------------------------------------------------------------
__device__ __forceinline__ void hmma_core_bb(const float* __restrict__ arow,
                                             const uint32_t* __restrict__ bh,
                                             const uint32_t* __restrict__ bl,
                                             float acc[2][4][4])
{
    extern __shared__ uint32_t sw[];
    const uint32_t sb = (uint32_t)__cvta_generic_to_shared(sw);
    const int tid  = threadIdx.x;
    const int lane = tid & 31, wid = tid >> 5;
    const int mo = (wid >> 1) * 32, no = (wid & 1) * 32;

    const int sar = tid >> 1;
    const int saw = (tid & 1) * 8;
    const int sbw = (tid >> 6) * 4;

    const int aoffw = (lane & 15) * WST + (lane >> 4) * 4;
    const int jj = lane >> 3, iL = lane & 7;
    const int boffw = ((jj >> 1) * 8 + iL) * WST + (jj & 1) * 4;

    float af[16];
    uint32_t bhw[4], blw[4];

    auto LOAD = [&](int kc) {
        const float* ap = arow + kc * 32;
        float4 v;
        v = *(const float4*)(ap + 0);  af[0] = v.x;  af[1] = v.y;  af[2] = v.z;  af[3] = v.w;
        v = *(const float4*)(ap + 4);  af[4] = v.x;  af[5] = v.y;  af[6] = v.z;  af[7] = v.w;
        v = *(const float4*)(ap + 8);  af[8] = v.x;  af[9] = v.y;  af[10] = v.z; af[11] = v.w;
        v = *(const float4*)(ap + 12); af[12] = v.x; af[13] = v.y; af[14] = v.z; af[15] = v.w;
        const int off = (kc * 16 + sbw) * 512;
        bhw[0] = bh[off];        bhw[1] = bh[off + 512];
        bhw[2] = bh[off + 1024]; bhw[3] = bh[off + 1536];
        blw[0] = bl[off];        blw[1] = bl[off + 512];
        blw[2] = bl[off + 1024]; blw[3] = bl[off + 1536];
    };

    auto STORE = [&](int bi) {
        uint32_t h[8], l[8];
#pragma unroll
        for (int j = 0; j < 8; j++) {
            h[j] = packbf(af[2 * j], af[2 * j + 1]);
            l[j] = packbf(af[2 * j] - lo_f(h[j]), af[2 * j + 1] - hi_f(h[j]));
        }
        uint32_t* pA = sw + bi * BUFW + sar * WST + saw;
        *(uint4*)pA        = make_uint4(h[0], h[1], h[2], h[3]);
        *(uint4*)(pA + 4)  = make_uint4(h[4], h[5], h[6], h[7]);
        uint32_t* pAl = pA + 2560;
        *(uint4*)pAl       = make_uint4(l[0], l[1], l[2], l[3]);
        *(uint4*)(pAl + 4) = make_uint4(l[4], l[5], l[6], l[7]);
        uint32_t* pB = sw + bi * BUFW + 5120 + (tid & 63) * WST + sbw;
        *(uint4*)pB          = make_uint4(bhw[0], bhw[1], bhw[2], bhw[3]);
        *(uint4*)(pB + 1280) = make_uint4(blw[0], blw[1], blw[2], blw[3]);
    };

    auto COMPUTE = [&](int bi) {
        const uint32_t base = sb + (uint32_t)(bi * BUFW) * 4u;
#pragma unroll
        for (int s = 0; s < 2; s++) {
            const int ws = s * 8;
            uint32_t aH[2][4], aL[2][4];
#pragma unroll
            for (int mf = 0; mf < 2; mf++) {
                const uint32_t wa = base + (uint32_t)(((mo + mf * 16) * WST + ws + aoffw) * 4);
                ldsm4(aH[mf][0], aH[mf][1], aH[mf][2], aH[mf][3], wa);
                ldsm4(aL[mf][0], aL[mf][1], aL[mf][2], aL[mf][3], wa + 2560u * 4u);
            }
#pragma unroll
            for (int p = 0; p < 2; p++) {
                const uint32_t wb = base +
                    (uint32_t)((5120 + (no + p * 16) * WST + ws + boffw) * 4);
                uint32_t h0, h1, h2, h3, l0, l1, l2, l3;
                ldsm4(h0, h1, h2, h3, wb);
                ldsm4(l0, l1, l2, l3, wb + 1280u * 4u);
#pragma unroll
                for (int mf = 0; mf < 2; mf++) {
                    mma16816(acc[mf][2 * p],     aH[mf], h0, h1);
                    mma16816(acc[mf][2 * p],     aH[mf], l0, l1);
                    mma16816(acc[mf][2 * p],     aL[mf], h0, h1);
                    mma16816(acc[mf][2 * p + 1], aH[mf], h2, h3);
                    mma16816(acc[mf][2 * p + 1], aH[mf], l2, l3);
                    mma16816(acc[mf][2 * p + 1], aL[mf], h2, h3);
                }
            }
        }
    };

    LOAD(0); STORE(0); __syncthreads();
    int cur = 0;
    for (int kc = 0; kc < 16; kc++) {
        if (kc < 15) LOAD(kc + 1);
        COMPUTE(cur);
        if (kc < 15) { STORE(cur ^ 1); __syncthreads(); cur ^= 1; }
    }
}

// ladder epilogue: fp32 C + B-style packed (row-pair shuffle)
__device__ __forceinline__ void ladder_epilogue(
    const float acc[2][4][4], int mrow, int bn,
    float* __restrict__ Cz, uint32_t* __restrict__ Dh, uint32_t* __restrict__ Dl)
{
    const int tid = threadIdx.x;
    const int lane = tid & 31, wid = tid >> 5;
    const int g = lane >> 2, qi = lane & 3;
    const int mo = (wid >> 1) * 32, no = (wid & 1) * 32;
#pragma unroll
    for (int mf = 0; mf < 2; mf++)
#pragma unroll
        for (int f = 0; f < 4; f++) {
            const int r0  = mrow + mo + mf * 16 + g;
            const int col = bn + no + f * 8 + 2 * qi;
            *(float2*)(Cz + (size_t)r0 * 512 + col) =
                make_float2(acc[mf][f][0], acc[mf][f][1]);
            *(float2*)(Cz + (size_t)(r0 + 8) * 512 + col) =
                make_float2(acc[mf][f][2], acc[mf][f][3]);

            float pc0 = __shfl_sync(0xffffffffu, acc[mf][f][0], (lane + 4) & 31);
            float pc1 = __shfl_sync(0xffffffffu, acc[mf][f][1], (lane + 4) & 31);
            float pc2 = __shfl_sync(0xffffffffu, acc[mf][f][2], (lane + 4) & 31);
            float pc3 = __shfl_sync(0xffffffffu, acc[mf][f][3], (lane + 4) & 31);
            if ((g & 1) == 0) {
                const int w0 = r0 >> 1;
                const int w1 = (r0 + 8) >> 1;
                uint32_t h0 = packbf(acc[mf][f][0], pc0);
                Dh[(size_t)w0 * 512 + col] = h0;
                Dl[(size_t)w0 * 512 + col] =
                    packbf(acc[mf][f][0] - lo_f(h0), pc0 - hi_f(h0));
                uint32_t h1 = packbf(acc[mf][f][1], pc1);
                Dh[(size_t)w0 * 512 + col + 1] = h1;
                Dl[(size_t)w0 * 512 + col + 1] =
                    packbf(acc[mf][f][1] - lo_f(h1), pc1 - hi_f(h1));
                uint32_t h2 = packbf(acc[mf][f][2], pc2);
                Dh[(size_t)w1 * 512 + col] = h2;
                Dl[(size_t)w1 * 512 + col] =
                    packbf(acc[mf][f][2] - lo_f(h2), pc2 - hi_f(h2));
                uint32_t h3 = packbf(acc[mf][f][3], pc3);
                Dh[(size_t)w1 * 512 + col + 1] = h3;
                Dl[(size_t)w1 * 512 + col + 1] =
                    packbf(acc[mf][f][3] - lo_f(h3), pc3 - hi_f(h3));
            }
        }
}

// ---------------------------------------------------------------------------
// generic C = A @ B (fp32 out).  grid (n/64, m/128).  Used for XW.
// ---------------------------------------------------------------------------
__global__ __launch_bounds__(256, 2) void hmma_gemm_bb(
    const float* __restrict__ A, const uint32_t* __restrict__ Bh,
    const uint32_t* __restrict__ Bl, float* __restrict__ C)
{
    const int bn = blockIdx.x * 64;
    const int bm = blockIdx.y * 128;
    const int tid = threadIdx.x;
    const float* arow = A + (size_t)(bm + (tid >> 1)) * 512 + (tid & 1) * 16;
    float acc[2][4][4] = {};
    hmma_core_bb(arow, Bh + bn + (tid & 63), Bl + bn + (tid & 63), acc);

    const int lane = tid & 31, wid = tid >> 5;
    const int g = lane >> 2, qi = lane & 3;
    const int mo = (wid >> 1) * 32, no = (wid & 1) * 32;
#pragma unroll
    for (int mf = 0; mf < 2; mf++)
#pragma unroll
        for (int f = 0; f < 4; f++) {
            const int r0  = bm + mo + mf * 16 + g;
            const int col = bn + no + f * 8 + 2 * qi;
            *(float2*)(C + (size_t)r0 * 512 + col) =
                make_float2(acc[mf][f][0], acc[mf][f][1]);
            *(float2*)(C + (size_t)(r0 + 8) * 512 + col) =
                make_float2(acc[mf][f][2], acc[mf][f][3]);
        }
}

// ---------------------------------------------------------------------------
// Mega pass1 step: y < 32 -> pass1 tile; y >= 32 (4 blocks) -> one ladder
// matrix product.  t == Lc-1 also seeds V0.  All operands via params.
// ---------------------------------------------------------------------------
__global__ __launch_bounds__(256, 2) void mega_step_kernel(
    const uint32_t* __restrict__ Rh, const uint32_t* __restrict__ Rl,
    float* __restrict__ O, int t, float* __restrict__ V0,
    const float* __restrict__ LA,
    const uint32_t* __restrict__ LBh, const uint32_t* __restrict__ LBl,
    float* __restrict__ LCf, uint32_t* __restrict__ LCh, uint32_t* __restrict__ LCl)
{
    const int bn  = blockIdx.x * 64;
    const int tid = threadIdx.x;

    if (blockIdx.y < 32) {
        const int bm = blockIdx.y * 128;
        const int srow = bm + (tid >> 1);
        const float* arow = O + ((size_t)(srow & 31) * Tn + (size_t)(srow >> 5) * Lc + (t - 1)) * 512
                            + (tid & 1) * 16;
        float acc[2][4][4] = {};
        hmma_core_bb(arow, Rh + bn + (tid & 63), Rl + bn + (tid & 63), acc);

        const int lane = tid & 31, wid = tid >> 5;
        const int g = lane >> 2, qi = lane & 3;
        const int mo = (wid >> 1) * 32, no = (wid & 1) * 32;
#pragma unroll
        for (int mf = 0; mf < 2; mf++)
#pragma unroll
            for (int f = 0; f < 4; f++) {
                const int col = bn + no + f * 8 + 2 * qi;
#pragma unroll
                for (int h = 0; h < 2; h++) {
                    const int r = bm + mo + mf * 16 + g + h * 8;
                    float* op = O + ((size_t)(r & 31) * Tn + (size_t)(r >> 5) * Lc + t) * 512 + col;
                    float2 e = *(float2*)op;
                    e.x += acc[mf][f][2 * h];
                    e.y += acc[mf][f][2 * h + 1];
                    *(float2*)op = e;
                    if (t == Lc - 1)
                        *(float2*)(V0 + (size_t)r * 512 + col) = e;
                }
            }
    } else {
        const int mrow = (blockIdx.y - 32) * 128;
        const float* arow = LA + (size_t)(mrow + (tid >> 1)) * 512 + (tid & 1) * 16;
        float acc[2][4][4] = {};
        hmma_core_bb(arow, LBh + bn + (tid & 63), LBl + bn + (tid & 63), acc);
        ladder_epilogue(acc, mrow, bn, LCf, LCh, LCl);
    }
}

// ---------------------------------------------------------------------------
// Scan step (+ optional ladder piggyback): y < 32 -> scan; y >= 32 -> ladder.
// scan: Vout[c] = Vin[c] + (c>=d ? Vin[c-d] @ S^d : 0)   (4096 rows)
// ---------------------------------------------------------------------------
__global__ __launch_bounds__(256, 2) void hmma_scan_step(
    float* __restrict__ Vout, const float* __restrict__ Vin,
    const uint32_t* __restrict__ Sh, const uint32_t* __restrict__ Sl, int d,
    const float* __restrict__ LA,
    const uint32_t* __restrict__ LBh, const uint32_t* __restrict__ LBl,
    float* __restrict__ LCf, uint32_t* __restrict__ LCh, uint32_t* __restrict__ LCl)
{
    const int bn  = blockIdx.x * 64;
    const int tid = threadIdx.x;

    if (blockIdx.y < 32) {
        const int bm = blockIdx.y * 128;
        const int srow = bm + (tid >> 1);
        const int csrc = (srow >> 5) - d;
        const int asrc = (csrc >= 0) ? (csrc * 32 + (srow & 31)) : srow;
        const float* arow = Vin + (size_t)asrc * 512 + (tid & 1) * 16;
        float acc[2][4][4] = {};
        hmma_core_bb(arow, Sh + bn + (tid & 63), Sl + bn + (tid & 63), acc);

        const int lane = tid & 31, wid = tid >> 5;
        const int g = lane >> 2, qi = lane & 3;
        const int mo = (wid >> 1) * 32, no = (wid & 1) * 32;
#pragma unroll
        for (int mf = 0; mf < 2; mf++)
#pragma unroll
            for (int f = 0; f < 4; f++) {
                const int col = bn + no + f * 8 + 2 * qi;
#pragma unroll
                for (int h = 0; h < 2; h++) {
                    const int r = bm + mo + mf * 16 + g + h * 8;
                    float2 e = *(const float2*)(Vin + (size_t)r * 512 + col);
                    if ((r >> 5) >= d) {
                        e.x += acc[mf][f][2 * h];
                        e.y += acc[mf][f][2 * h + 1];
                    }
                    *(float2*)(Vout + (size_t)r * 512 + col) = e;
                }
            }
    } else {
        const int mrow = (blockIdx.y - 32) * 128;
        const float* arow = LA + (size_t)(mrow + (tid >> 1)) * 512 + (tid & 1) * 16;
        float acc[2][4][4] = {};
        hmma_core_bb(arow, LBh + bn + (tid & 63), LBl + bn + (tid & 63), acc);
        ladder_epilogue(acc, mrow, bn, LCf, LCh, LCl);
    }
}

// ---------------------------------------------------------------------------
// pass3: O[b, 8*(c+1)+t, :] += V[c] @ R^{t+1}.  grid (8, 32, 8: t)
// ---------------------------------------------------------------------------
__global__ __launch_bounds__(256, 2) void hmma_pass3_bb(
    float* __restrict__ O, const float* __restrict__ V,
    const uint32_t* __restrict__ Rh, const uint32_t* __restrict__ Rl)
{
    const int t  = blockIdx.z;
    const int bn = blockIdx.x * 64;
    const int bm = blockIdx.y * 128;
    const int tid = threadIdx.x;
    const float* arow = V + (size_t)(bm + (tid >> 1)) * 512 + (tid & 1) * 16;
    float acc[2][4][4] = {};
    hmma_core_bb(arow, Rh + (size_t)t * SZW + bn + (tid & 63),
                 Rl + (size_t)t * SZW + bn + (tid & 63), acc);

    const int lane = tid & 31, wid = tid >> 5;
    const int g = lane >> 2, qi = lane & 3;
    const int mo = (wid >> 1) * 32, no = (wid & 1) * 32;
#pragma unroll
    for (int mf = 0; mf < 2; mf++)
#pragma unroll
        for (int f = 0; f < 4; f++) {
            const int col = bn + no + f * 8 + 2 * qi;
#pragma unroll
            for (int h = 0; h < 2; h++) {
                const int r = bm + mo + mf * 16 + g + h * 8;
                const int cidx = r >> 5;       // = c-1
                if (cidx < Cc - 1) {
                    const int b = r & 31;
                    float* op = O + ((size_t)b * Tn + (size_t)(cidx + 1) * Lc + t) * 512 + col;
                    float2 e = *(float2*)op;
                    e.x += acc[mf][f][2 * h];
                    e.y += acc[mf][f][2 * h + 1];
                    *(float2*)op = e;
                }
            }
        }
}

// ---------------------------------------------------------------------------
// Merged prologue: pack W (blocks 0-511), pack R (512-1023), copy R->Rf
// (1024-1279).
// ---------------------------------------------------------------------------
__global__ void prologue_kernel(const float* __restrict__ w,
                                const float* __restrict__ r,
                                uint32_t* __restrict__ Wh, uint32_t* __restrict__ Wl,
                                uint32_t* __restrict__ Rh, uint32_t* __restrict__ Rl,
                                float* __restrict__ Rf)
{
    const int bid = blockIdx.x;
    if (bid < 1024) {
        const bool isW = bid < 512;
        const float* src = isW ? w : r;
        uint32_t* dh = isW ? Wh : Rh;
        uint32_t* dl = isW ? Wl : Rl;
        const int i = (isW ? bid : bid - 512) * 256 + threadIdx.x;
        const int ww = i >> 9, n = i & 511;
        const float* s = src + (size_t)(2 * ww) * 512 + n;
        const float s0 = s[0], s1 = s[512];
        const uint32_t h = packbf(s0, s1);
        dh[i] = h;
        dl[i] = packbf(s0 - lo_f(h), s1 - hi_f(h));
    } else {
        const int i = (bid - 1024) * 256 + threadIdx.x;
        ((float4*)Rf)[i] = ((const float4*)r)[i];
    }
}

// ---------------------------------------------------------------------------
// Launch sequence
// ---------------------------------------------------------------------------
extern "C" void kernel_launch(void* const* d_in, const int* in_sizes, int n_in,
                              void* d_out, int out_size)
{
    const float* x = (const float*)d_in[0];
    const float* w = (const float*)d_in[1];
    const float* r = (const float*)d_in[2];
    float* o = (float*)d_out;
    (void)in_sizes; (void)n_in; (void)out_size;

    float *Rf, *Sf, *V0, *V1;
    uint32_t *Rh, *Rl, *Sh, *Sl, *Wh, *Wl;
    cudaGetSymbolAddress((void**)&Rf, g_Rf);
    cudaGetSymbolAddress((void**)&Rh, g_Rh);
    cudaGetSymbolAddress((void**)&Rl, g_Rl);
    cudaGetSymbolAddress((void**)&Sf, g_Sf);
    cudaGetSymbolAddress((void**)&Sh, g_Sh);
    cudaGetSymbolAddress((void**)&Sl, g_Sl);
    cudaGetSymbolAddress((void**)&Wh, g_Wh);
    cudaGetSymbolAddress((void**)&Wl, g_Wl);
    cudaGetSymbolAddress((void**)&V0, g_V0);
    cudaGetSymbolAddress((void**)&V1, g_V1);

    cudaFuncSetAttribute(hmma_gemm_bb,     cudaFuncAttributeMaxDynamicSharedMemorySize, SMEM_BYTES);
    cudaFuncSetAttribute(mega_step_kernel, cudaFuncAttributeMaxDynamicSharedMemorySize, SMEM_BYTES);
    cudaFuncSetAttribute(hmma_scan_step,   cudaFuncAttributeMaxDynamicSharedMemorySize, SMEM_BYTES);
    cudaFuncSetAttribute(hmma_pass3_bb,    cudaFuncAttributeMaxDynamicSharedMemorySize, SMEM_BYTES);

    // Prologue (one kernel): pack W, pack R, seed Rf with R^1.
    prologue_kernel<<<1280, 256>>>(w, r, Wh, Wl, Rh, Rl, Rf);

    // Phase A: O = X @ W
    hmma_gemm_bb<<<dim3(8, M / 128), 256, SMEM_BYTES>>>(x, Wh, Wl, o);

    // Ladder: ONE matrix product per step slot (4 extra y-blocks -> grid 288).
    struct Lad { const float* A; const uint32_t *Bh, *Bl; float* Cf; uint32_t *Ch, *Cl; };
    Lad lad1[8];
    lad1[1] = {Rf,          Rh,           Rl,           Rf + (size_t)1 * SZ, Rh + 1 * SZW, Rl + 1 * SZW};  // R^2 = R@R
    lad1[2] = {Rf,          Rh + 1 * SZW, Rl + 1 * SZW, Rf + (size_t)2 * SZ, Rh + 2 * SZW, Rl + 2 * SZW};  // R^3 = R@R^2
    lad1[3] = {Rf + 1 * SZ, Rh + 1 * SZW, Rl + 1 * SZW, Rf + (size_t)3 * SZ, Rh + 3 * SZW, Rl + 3 * SZW};  // R^4 = R^2@R^2
    lad1[4] = {Rf,          Rh + 3 * SZW, Rl + 3 * SZW, Rf + (size_t)4 * SZ, Rh + 4 * SZW, Rl + 4 * SZW};  // R^5 = R@R^4
    lad1[5] = {Rf + 1 * SZ, Rh + 3 * SZW, Rl + 3 * SZW, Rf + (size_t)5 * SZ, Rh + 5 * SZW, Rl + 5 * SZW};  // R^6 = R^2@R^4
    lad1[6] = {Rf + 2 * SZ, Rh + 3 * SZW, Rl + 3 * SZW, Rf + (size_t)6 * SZ, Rh + 6 * SZW, Rl + 6 * SZW};  // R^7 = R^3@R^4
    lad1[7] = {Rf + 3 * SZ, Rh + 3 * SZW, Rl + 3 * SZW, Rf + (size_t)7 * SZ, Rh + 7 * SZW, Rl + 7 * SZW};  // R^8 = R^4@R^4

    // Phase C + B: 7 pass1 steps, each with one piggybacked ladder product
    for (int t = 1; t < Lc; t++) {
        const Lad& L = lad1[t];
        mega_step_kernel<<<dim3(8, 36), 256, SMEM_BYTES>>>(
            Rh, Rl, o, t, V0, L.A, L.Bh, L.Bl, L.Cf, L.Ch, L.Cl);
    }

    // Scan-slot ladder: S^2..S^64 (S = R^8), one per slot i=0..5.
    Lad lads[7];
    lads[0] = {Rf + 7 * SZ, Rh + 7 * SZW, Rl + 7 * SZW, Sf,                  Sh,           Sl};            // S^2
    lads[1] = {Sf,          Sh,           Sl,           Sf + (size_t)1 * SZ, Sh + 1 * SZW, Sl + 1 * SZW};  // S^4
    lads[2] = {Sf + 1 * SZ, Sh + 1 * SZW, Sl + 1 * SZW, Sf + (size_t)2 * SZ, Sh + 2 * SZW, Sl + 2 * SZW};  // S^8
    lads[3] = {Sf + 2 * SZ, Sh + 2 * SZW, Sl + 2 * SZW, Sf + (size_t)3 * SZ, Sh + 3 * SZW, Sl + 3 * SZW};  // S^16
    lads[4] = {Sf + 3 * SZ, Sh + 3 * SZW, Sl + 3 * SZW, Sf + (size_t)4 * SZ, Sh + 4 * SZW, Sl + 4 * SZW};  // S^32
    lads[5] = {Sf + 4 * SZ, Sh + 4 * SZW, Sl + 4 * SZW, Sf + (size_t)5 * SZ, Sh + 5 * SZW, Sl + 5 * SZW};  // S^64
    lads[6] = lads[5];  // unused slot

    // Phase D: carry scan, 7 steps; step i uses S^{2^i} (i=0 -> R^8).
    const float* vin = V0;
    float* vout = V1;
    for (int i = 0; i < 7; i++) {
        const int d = 1 << i;
        const uint32_t* Sph = (i == 0) ? (Rh + (size_t)7 * SZW) : (Sh + (size_t)(i - 1) * SZW);
        const uint32_t* Spl = (i == 0) ? (Rl + (size_t)7 * SZW) : (Sl + (size_t)(i - 1) * SZW);
        const int lext = (i < 6) ? 4 : 0;
        const Lad& L = lads[i];
        hmma_scan_step<<<dim3(8, 32 + lext), 256, SMEM_BYTES>>>(
            vout, vin, Sph, Spl, d, L.A, L.Bh, L.Bl, L.Cf, L.Ch, L.Cl);
        const float* tmp = vin; vin = vout; vout = (float*)tmp;
    }

    // Phase E: batched correction (t = 0..7)
    hmma_pass3_bb<<<dim3(8, 32, Lc), 256, SMEM_BYTES>>>(o, vin, Rh, Rl);
}

// round 16
// speedup vs baseline: 1.5371x; 1.0205x over previous
#include <cuda_runtime.h>
#include <cuda_bf16.h>
#include <cstdint>

namespace {
constexpr int Bn = 32;
constexpr int Tn = 1024;
constexpr int M  = Bn * 1024;

constexpr int Lc = 8;
constexpr int Cc = Tn / Lc;         // 128

constexpr int SZ  = 512 * 512;      // fp32 elements per matrix
constexpr int SZW = 256 * 512;      // packed bf16x2 words per matrix
constexpr int WST = 20;             // smem row stride in words
constexpr int BUFW = 7680;          // Ah 2560 | Al 2560 | Bh 1280 | Bl 1280
constexpr int SMEM_BYTES = 2 * BUFW * 4;   // 61440
}

// ---------------------------------------------------------------------------
// Static device scratch
// ---------------------------------------------------------------------------
__device__ float    g_Rf[8 * SZ];       // R^1..R^8 fp32
__device__ uint32_t g_Rh[8 * SZW];      // R^1..R^8 B-style packed hi
__device__ uint32_t g_Rl[8 * SZW];
__device__ float    g_Sf[6 * SZ];       // S^2,S^4,S^8,S^16,S^32,S^64 (S = R^8)
__device__ uint32_t g_Sh[6 * SZW];
__device__ uint32_t g_Sl[6 * SZW];
__device__ uint32_t g_Wh[SZW];
__device__ uint32_t g_Wl[SZW];
__device__ float    g_V0[Cc * Bn * 512];   // 4096 x 512
__device__ float    g_V1[Cc * Bn * 512];
__device__ int      g_flagP[8][32];        // pass1 step-t / row-group counters
__device__ int      g_lflag[8];            // ladder product counters

// ---------------------------------------------------------------------------
// helpers
// ---------------------------------------------------------------------------
__device__ __forceinline__ uint32_t packbf(float a, float b) {
    uint32_t r;  // low half = a, high half = b
    asm("cvt.rn.bf16x2.f32 %0, %1, %2;" : "=r"(r) : "f"(b), "f"(a));
    return r;
}
__device__ __forceinline__ float lo_f(uint32_t p) { return __uint_as_float(p << 16); }
__device__ __forceinline__ float hi_f(uint32_t p) { return __uint_as_float(p & 0xFFFF0000u); }

__device__ __forceinline__ void mma16816(float* c, const uint32_t* a,
                                         uint32_t b0, uint32_t b1) {
    asm volatile(
        "mma.sync.aligned.m16n8k16.row.col.f32.bf16.bf16.f32 "
        "{%0,%1,%2,%3}, {%4,%5,%6,%7}, {%8,%9}, {%0,%1,%2,%3};"
        : "+f"(c[0]), "+f"(c[1]), "+f"(c[2]), "+f"(c[3])
        : "r"(a[0]), "r"(a[1]), "r"(a[2]), "r"(a[3]), "r"(b0), "r"(b1));
}

__device__ __forceinline__ void ldsm4(uint32_t& r0, uint32_t& r1,
                                      uint32_t& r2, uint32_t& r3, uint32_t addr) {
    asm volatile(
        "ldmatrix.sync.aligned.m8n8.x4.shared.b16 {%0,%1,%2,%3}, [%4];"
        : "=r"(r0), "=r"(r1), "=r"(r2), "=r"(r3) : "r"(addr));
}

__device__ __forceinline__ void spin_until(volatile int* p, int v) {
    while (*p < v) { __nanosleep(64); }
}

// ---------------------------------------------------------------------------
// Double-buffered HMMA core (fp32 A converted in-kernel, pre-packed B,
// ldmatrix fragment loads).
// ---------------------------------------------------------------------------
__device__ __forceinline__ void hmma_core_bb(const float* __restrict__ arow,
                                             const uint32_t* __restrict__ bh,
                                             const uint32_t* __restrict__ bl,
                                             float acc[2][4][4])
{
    extern __shared__ uint32_t sw[];
    const uint32_t sb = (uint32_t)__cvta_generic_to_shared(sw);
    const int tid  = threadIdx.x;
    const int lane = tid & 31, wid = tid >> 5;
    const int mo = (wid >> 1) * 32, no = (wid & 1) * 32;

    const int sar = tid >> 1;
    const int saw = (tid & 1) * 8;
    const int sbw = (tid >> 6) * 4;

    const int aoffw = (lane & 15) * WST + (lane >> 4) * 4;
    const int jj = lane >> 3, iL = lane & 7;
    const int boffw = ((jj >> 1) * 8 + iL) * WST + (jj & 1) * 4;

    float af[16];
    uint32_t bhw[4], blw[4];

    auto LOAD = [&](int kc) {
        const float* ap = arow + kc * 32;
        float4 v;
        v = *(const float4*)(ap + 0);  af[0] = v.x;  af[1] = v.y;  af[2] = v.z;  af[3] = v.w;
        v = *(const float4*)(ap + 4);  af[4] = v.x;  af[5] = v.y;  af[6] = v.z;  af[7] = v.w;
        v = *(const float4*)(ap + 8);  af[8] = v.x;  af[9] = v.y;  af[10] = v.z; af[11] = v.w;
        v = *(const float4*)(ap + 12); af[12] = v.x; af[13] = v.y; af[14] = v.z; af[15] = v.w;
        const int off = (kc * 16 + sbw) * 512;
        bhw[0] = bh[off];        bhw[1] = bh[off + 512];
        bhw[2] = bh[off + 1024]; bhw[3] = bh[off + 1536];
        blw[0] = bl[off];        blw[1] = bl[off + 512];
        blw[2] = bl[off + 1024]; blw[3] = bl[off + 1536];
    };

    auto STORE = [&](int bi) {
        uint32_t h[8], l[8];
#pragma unroll
        for (int j = 0; j < 8; j++) {
            h[j] = packbf(af[2 * j], af[2 * j + 1]);
            l[j] = packbf(af[2 * j] - lo_f(h[j]), af[2 * j + 1] - hi_f(h[j]));
        }
        uint32_t* pA = sw + bi * BUFW + sar * WST + saw;
        *(uint4*)pA        = make_uint4(h[0], h[1], h[2], h[3]);
        *(uint4*)(pA + 4)  = make_uint4(h[4], h[5], h[6], h[7]);
        uint32_t* pAl = pA + 2560;
        *(uint4*)pAl       = make_uint4(l[0], l[1], l[2], l[3]);
        *(uint4*)(pAl + 4) = make_uint4(l[4], l[5], l[6], l[7]);
        uint32_t* pB = sw + bi * BUFW + 5120 + (tid & 63) * WST + sbw;
        *(uint4*)pB          = make_uint4(bhw[0], bhw[1], bhw[2], bhw[3]);
        *(uint4*)(pB + 1280) = make_uint4(blw[0], blw[1], blw[2], blw[3]);
    };

    auto COMPUTE = [&](int bi) {
        const uint32_t base = sb + (uint32_t)(bi * BUFW) * 4u;
#pragma unroll
        for (int s = 0; s < 2; s++) {
            const int ws = s * 8;
            uint32_t aH[2][4], aL[2][4];
#pragma unroll
            for (int mf = 0; mf < 2; mf++) {
                const uint32_t wa = base + (uint32_t)(((mo + mf * 16) * WST + ws + aoffw) * 4);
                ldsm4(aH[mf][0], aH[mf][1], aH[mf][2], aH[mf][3], wa);
                ldsm4(aL[mf][0], aL[mf][1], aL[mf][2], aL[mf][3], wa + 2560u * 4u);
            }
#pragma unroll
            for (int p = 0; p < 2; p++) {
                const uint32_t wb = base +
                    (uint32_t)((5120 + (no + p * 16) * WST + ws + boffw) * 4);
                uint32_t h0, h1, h2, h3, l0, l1, l2, l3;
                ldsm4(h0, h1, h2, h3, wb);
                ldsm4(l0, l1, l2, l3, wb + 1280u * 4u);
#pragma unroll
                for (int mf = 0; mf < 2; mf++) {
                    mma16816(acc[mf][2 * p],     aH[mf], h0, h1);
                    mma16816(acc[mf][2 * p],     aH[mf], l0, l1);
                    mma16816(acc[mf][2 * p],     aL[mf], h0, h1);
                    mma16816(acc[mf][2 * p + 1], aH[mf], h2, h3);
                    mma16816(acc[mf][2 * p + 1], aH[mf], l2, l3);
                    mma16816(acc[mf][2 * p + 1], aL[mf], h2, h3);
                }
            }
        }
    };

    LOAD(0); STORE(0); __syncthreads();
    int cur = 0;
    for (int kc = 0; kc < 16; kc++) {
        if (kc < 15) LOAD(kc + 1);
        COMPUTE(cur);
        if (kc < 15) { STORE(cur ^ 1); __syncthreads(); cur ^= 1; }
    }
}

// ladder epilogue: fp32 C + B-style packed (row-pair shuffle)
__device__ __forceinline__ void ladder_epilogue(
    const float acc[2][4][4], int mrow, int bn,
    float* __restrict__ Cz, uint32_t* __restrict__ Dh, uint32_t* __restrict__ Dl)
{
    const int tid = threadIdx.x;
    const int lane = tid & 31, wid = tid >> 5;
    const int g = lane >> 2, qi = lane & 3;
    const int mo = (wid >> 1) * 32, no = (wid & 1) * 32;
#pragma unroll
    for (int mf = 0; mf < 2; mf++)
#pragma unroll
        for (int f = 0; f < 4; f++) {
            const int r0  = mrow + mo + mf * 16 + g;
            const int col = bn + no + f * 8 + 2 * qi;
            *(float2*)(Cz + (size_t)r0 * 512 + col) =
                make_float2(acc[mf][f][0], acc[mf][f][1]);
            *(float2*)(Cz + (size_t)(r0 + 8) * 512 + col) =
                make_float2(acc[mf][f][2], acc[mf][f][3]);

            float pc0 = __shfl_sync(0xffffffffu, acc[mf][f][0], (lane + 4) & 31);
            float pc1 = __shfl_sync(0xffffffffu, acc[mf][f][1], (lane + 4) & 31);
            float pc2 = __shfl_sync(0xffffffffu, acc[mf][f][2], (lane + 4) & 31);
            float pc3 = __shfl_sync(0xffffffffu, acc[mf][f][3], (lane + 4) & 31);
            if ((g & 1) == 0) {
                const int w0 = r0 >> 1;
                const int w1 = (r0 + 8) >> 1;
                uint32_t h0 = packbf(acc[mf][f][0], pc0);
                Dh[(size_t)w0 * 512 + col] = h0;
                Dl[(size_t)w0 * 512 + col] =
                    packbf(acc[mf][f][0] - lo_f(h0), pc0 - hi_f(h0));
                uint32_t h1 = packbf(acc[mf][f][1], pc1);
                Dh[(size_t)w0 * 512 + col + 1] = h1;
                Dl[(size_t)w0 * 512 + col + 1] =
                    packbf(acc[mf][f][1] - lo_f(h1), pc1 - hi_f(h1));
                uint32_t h2 = packbf(acc[mf][f][2], pc2);
                Dh[(size_t)w1 * 512 + col] = h2;
                Dl[(size_t)w1 * 512 + col] =
                    packbf(acc[mf][f][2] - lo_f(h2), pc2 - hi_f(h2));
                uint32_t h3 = packbf(acc[mf][f][3], pc3);
                Dh[(size_t)w1 * 512 + col + 1] = h3;
                Dl[(size_t)w1 * 512 + col + 1] =
                    packbf(acc[mf][f][3] - lo_f(h3), pc3 - hi_f(h3));
            }
        }
}

// ---------------------------------------------------------------------------
// generic C = A @ B (fp32 out).  grid (n/64, m/128).  Used for XW.
// ---------------------------------------------------------------------------
__global__ __launch_bounds__(256, 2) void hmma_gemm_bb(
    const float* __restrict__ A, const uint32_t* __restrict__ Bh,
    const uint32_t* __restrict__ Bl, float* __restrict__ C)
{
    const int bn = blockIdx.x * 64;
    const int bm = blockIdx.y * 128;
    const int tid = threadIdx.x;
    const float* arow = A + (size_t)(bm + (tid >> 1)) * 512 + (tid & 1) * 16;
    float acc[2][4][4] = {};
    hmma_core_bb(arow, Bh + bn + (tid & 63), Bl + bn + (tid & 63), acc);

    const int lane = tid & 31, wid = tid >> 5;
    const int g = lane >> 2, qi = lane & 3;
    const int mo = (wid >> 1) * 32, no = (wid & 1) * 32;
#pragma unroll
    for (int mf = 0; mf < 2; mf++)
#pragma unroll
        for (int f = 0; f < 4; f++) {
            const int r0  = bm + mo + mf * 16 + g;
            const int col = bn + no + f * 8 + 2 * qi;
            *(float2*)(C + (size_t)r0 * 512 + col) =
                make_float2(acc[mf][f][0], acc[mf][f][1]);
            *(float2*)(C + (size_t)(r0 + 8) * 512 + col) =
                make_float2(acc[mf][f][2], acc[mf][f][3]);
        }
}

// ---------------------------------------------------------------------------
// Persistent pass1: ONE launch, grid (8, 36), loops t = 1..7 internally.
//   y < 32 -> pass1 tiles, gated on flagP[t-1][y] (8 producers per group)
//   y >= 32 -> ladder products R^2..R^8, gated on lflag of producing slots
// t == 7 also seeds V0.
// ---------------------------------------------------------------------------
__global__ __launch_bounds__(256, 2) void pass1_persist_kernel(
    const uint32_t* __restrict__ Rh, const uint32_t* __restrict__ Rl,
    float* __restrict__ O, float* __restrict__ V0,
    float* Rfb, uint32_t* Rhb, uint32_t* Rlb)
{
    const int bn  = blockIdx.x * 64;
    const int y   = blockIdx.y;
    const int tid = threadIdx.x;
    const bool isPass = (y < 32);

    // ladder schedule (indexed by t): A slot (fp32), B slot (packed), C slot = t
    const int aslot[8] = {0, 0, 0, 1, 0, 1, 2, 3};
    const int bslot[8] = {0, 0, 1, 1, 3, 3, 3, 3};

    for (int t = 1; t < Lc; t++) {
        // ---- dependency wait ----
        if (isPass) {
            if (t > 1) {
                if (tid == 0) spin_until(&g_flagP[t - 1][y], 8);
                __syncthreads();
                __threadfence();
            }
        } else {
            if (t > 1) {
                if (tid == 0) {
                    if (aslot[t] > 0) spin_until(&g_lflag[aslot[t]], 32);
                    if (bslot[t] > 0) spin_until(&g_lflag[bslot[t]], 32);
                }
                __syncthreads();
                __threadfence();
            }
        }

        // ---- work ----
        if (isPass) {
            const int bm = y * 128;
            const int srow = bm + (tid >> 1);
            const float* arow = O + ((size_t)(srow & 31) * Tn + (size_t)(srow >> 5) * Lc + (t - 1)) * 512
                                + (tid & 1) * 16;
            float acc[2][4][4] = {};
            hmma_core_bb(arow, Rh + bn + (tid & 63), Rl + bn + (tid & 63), acc);

            const int lane = tid & 31, wid = tid >> 5;
            const int g = lane >> 2, qi = lane & 3;
            const int mo = (wid >> 1) * 32, no = (wid & 1) * 32;
#pragma unroll
            for (int mf = 0; mf < 2; mf++)
#pragma unroll
                for (int f = 0; f < 4; f++) {
                    const int col = bn + no + f * 8 + 2 * qi;
#pragma unroll
                    for (int h = 0; h < 2; h++) {
                        const int r = bm + mo + mf * 16 + g + h * 8;
                        float* op = O + ((size_t)(r & 31) * Tn + (size_t)(r >> 5) * Lc + t) * 512 + col;
                        float2 e = *(float2*)op;
                        e.x += acc[mf][f][2 * h];
                        e.y += acc[mf][f][2 * h + 1];
                        *(float2*)op = e;
                        if (t == Lc - 1)
                            *(float2*)(V0 + (size_t)r * 512 + col) = e;
                    }
                }
        } else {
            const int mrow = (y - 32) * 128;
            const float*    LA  = Rfb + (size_t)aslot[t] * SZ;
            const uint32_t* LBh = Rhb + (size_t)bslot[t] * SZW;
            const uint32_t* LBl = Rlb + (size_t)bslot[t] * SZW;
            const float* arow = LA + (size_t)(mrow + (tid >> 1)) * 512 + (tid & 1) * 16;
            float acc[2][4][4] = {};
            hmma_core_bb(arow, LBh + bn + (tid & 63), LBl + bn + (tid & 63), acc);
            ladder_epilogue(acc, mrow, bn, Rfb + (size_t)t * SZ,
                            Rhb + (size_t)t * SZW, Rlb + (size_t)t * SZW);
        }

        // ---- publish ----
        __threadfence();
        __syncthreads();
        if (tid == 0) {
            if (isPass) atomicAdd(&g_flagP[t][y], 1);
            else        atomicAdd(&g_lflag[t], 1);
        }
    }
}

// ---------------------------------------------------------------------------
// Scan step (+ optional ladder piggyback): y < 32 -> scan; y >= 32 -> ladder.
// scan: Vout[c] = Vin[c] + (c>=d ? Vin[c-d] @ S^d : 0)   (4096 rows)
// ---------------------------------------------------------------------------
__global__ __launch_bounds__(256, 2) void hmma_scan_step(
    float* __restrict__ Vout, const float* __restrict__ Vin,
    const uint32_t* __restrict__ Sh, const uint32_t* __restrict__ Sl, int d,
    const float* __restrict__ LA,
    const uint32_t* __restrict__ LBh, const uint32_t* __restrict__ LBl,
    float* __restrict__ LCf, uint32_t* __restrict__ LCh, uint32_t* __restrict__ LCl)
{
    const int bn  = blockIdx.x * 64;
    const int tid = threadIdx.x;

    if (blockIdx.y < 32) {
        const int bm = blockIdx.y * 128;
        const int srow = bm + (tid >> 1);
        const int csrc = (srow >> 5) - d;
        const int asrc = (csrc >= 0) ? (csrc * 32 + (srow & 31)) : srow;
        const float* arow = Vin + (size_t)asrc * 512 + (tid & 1) * 16;
        float acc[2][4][4] = {};
        hmma_core_bb(arow, Sh + bn + (tid & 63), Sl + bn + (tid & 63), acc);

        const int lane = tid & 31, wid = tid >> 5;
        const int g = lane >> 2, qi = lane & 3;
        const int mo = (wid >> 1) * 32, no = (wid & 1) * 32;
#pragma unroll
        for (int mf = 0; mf < 2; mf++)
#pragma unroll
            for (int f = 0; f < 4; f++) {
                const int col = bn + no + f * 8 + 2 * qi;
#pragma unroll
                for (int h = 0; h < 2; h++) {
                    const int r = bm + mo + mf * 16 + g + h * 8;
                    float2 e = *(const float2*)(Vin + (size_t)r * 512 + col);
                    if ((r >> 5) >= d) {
                        e.x += acc[mf][f][2 * h];
                        e.y += acc[mf][f][2 * h + 1];
                    }
                    *(float2*)(Vout + (size_t)r * 512 + col) = e;
                }
            }
    } else {
        const int mrow = (blockIdx.y - 32) * 128;
        const float* arow = LA + (size_t)(mrow + (tid >> 1)) * 512 + (tid & 1) * 16;
        float acc[2][4][4] = {};
        hmma_core_bb(arow, LBh + bn + (tid & 63), LBl + bn + (tid & 63), acc);
        ladder_epilogue(acc, mrow, bn, LCf, LCh, LCl);
    }
}

// ---------------------------------------------------------------------------
// pass3: O[b, 8*(c+1)+t, :] += V[c] @ R^{t+1}.  grid (8, 32, 8: t)
// ---------------------------------------------------------------------------
__global__ __launch_bounds__(256, 2) void hmma_pass3_bb(
    float* __restrict__ O, const float* __restrict__ V,
    const uint32_t* __restrict__ Rh, const uint32_t* __restrict__ Rl)
{
    const int t  = blockIdx.z;
    const int bn = blockIdx.x * 64;
    const int bm = blockIdx.y * 128;
    const int tid = threadIdx.x;
    const float* arow = V + (size_t)(bm + (tid >> 1)) * 512 + (tid & 1) * 16;
    float acc[2][4][4] = {};
    hmma_core_bb(arow, Rh + (size_t)t * SZW + bn + (tid & 63),
                 Rl + (size_t)t * SZW + bn + (tid & 63), acc);

    const int lane = tid & 31, wid = tid >> 5;
    const int g = lane >> 2, qi = lane & 3;
    const int mo = (wid >> 1) * 32, no = (wid & 1) * 32;
#pragma unroll
    for (int mf = 0; mf < 2; mf++)
#pragma unroll
        for (int f = 0; f < 4; f++) {
            const int col = bn + no + f * 8 + 2 * qi;
#pragma unroll
            for (int h = 0; h < 2; h++) {
                const int r = bm + mo + mf * 16 + g + h * 8;
                const int cidx = r >> 5;       // = c-1
                if (cidx < Cc - 1) {
                    const int b = r & 31;
                    float* op = O + ((size_t)b * Tn + (size_t)(cidx + 1) * Lc + t) * 512 + col;
                    float2 e = *(float2*)op;
                    e.x += acc[mf][f][2 * h];
                    e.y += acc[mf][f][2 * h + 1];
                    *(float2*)op = e;
                }
            }
        }
}

// ---------------------------------------------------------------------------
// Merged prologue: pack W (blocks 0-511), pack R (512-1023), copy R->Rf
// (1024-1279).  Block 0 also zeroes the persistent-kernel flags.
// ---------------------------------------------------------------------------
__global__ void prologue_kernel(const float* __restrict__ w,
                                const float* __restrict__ r,
                                uint32_t* __restrict__ Wh, uint32_t* __restrict__ Wl,
                                uint32_t* __restrict__ Rh, uint32_t* __restrict__ Rl,
                                float* __restrict__ Rf)
{
    const int bid = blockIdx.x;
    if (bid == 0) {
        ((int*)g_flagP)[threadIdx.x] = 0;           // 256 ints exactly
        if (threadIdx.x < 8) g_lflag[threadIdx.x] = 0;
    }
    if (bid < 1024) {
        const bool isW = bid < 512;
        const float* src = isW ? w : r;
        uint32_t* dh = isW ? Wh : Rh;
        uint32_t* dl = isW ? Wl : Rl;
        const int i = (isW ? bid : bid - 512) * 256 + threadIdx.x;
        const int ww = i >> 9, n = i & 511;
        const float* s = src + (size_t)(2 * ww) * 512 + n;
        const float s0 = s[0], s1 = s[512];
        const uint32_t h = packbf(s0, s1);
        dh[i] = h;
        dl[i] = packbf(s0 - lo_f(h), s1 - hi_f(h));
    } else {
        const int i = (bid - 1024) * 256 + threadIdx.x;
        ((float4*)Rf)[i] = ((const float4*)r)[i];
    }
}

// ---------------------------------------------------------------------------
// Launch sequence
// ---------------------------------------------------------------------------
extern "C" void kernel_launch(void* const* d_in, const int* in_sizes, int n_in,
                              void* d_out, int out_size)
{
    const float* x = (const float*)d_in[0];
    const float* w = (const float*)d_in[1];
    const float* r = (const float*)d_in[2];
    float* o = (float*)d_out;
    (void)in_sizes; (void)n_in; (void)out_size;

    float *Rf, *Sf, *V0, *V1;
    uint32_t *Rh, *Rl, *Sh, *Sl, *Wh, *Wl;
    cudaGetSymbolAddress((void**)&Rf, g_Rf);
    cudaGetSymbolAddress((void**)&Rh, g_Rh);
    cudaGetSymbolAddress((void**)&Rl, g_Rl);
    cudaGetSymbolAddress((void**)&Sf, g_Sf);
    cudaGetSymbolAddress((void**)&Sh, g_Sh);
    cudaGetSymbolAddress((void**)&Sl, g_Sl);
    cudaGetSymbolAddress((void**)&Wh, g_Wh);
    cudaGetSymbolAddress((void**)&Wl, g_Wl);
    cudaGetSymbolAddress((void**)&V0, g_V0);
    cudaGetSymbolAddress((void**)&V1, g_V1);

    cudaFuncSetAttribute(hmma_gemm_bb,        cudaFuncAttributeMaxDynamicSharedMemorySize, SMEM_BYTES);
    cudaFuncSetAttribute(pass1_persist_kernel, cudaFuncAttributeMaxDynamicSharedMemorySize, SMEM_BYTES);
    cudaFuncSetAttribute(hmma_scan_step,      cudaFuncAttributeMaxDynamicSharedMemorySize, SMEM_BYTES);
    cudaFuncSetAttribute(hmma_pass3_bb,       cudaFuncAttributeMaxDynamicSharedMemorySize, SMEM_BYTES);

    // Prologue (one kernel): pack W, pack R, seed Rf with R^1, zero flags.
    prologue_kernel<<<1280, 256>>>(w, r, Wh, Wl, Rh, Rl, Rf);

    // Phase A: O = X @ W
    hmma_gemm_bb<<<dim3(8, M / 128), 256, SMEM_BYTES>>>(x, Wh, Wl, o);

    // Phase C + B: ONE persistent launch covering all 7 pass1 steps +
    // the R-power ladder, with fine-grained row-group flags.
    pass1_persist_kernel<<<dim3(8, 36), 256, SMEM_BYTES>>>(
        Rh, Rl, o, V0, Rf, Rh, Rl);

    // Scan-slot ladder: S^2..S^64 (S = R^8), one per slot i=0..5.
    struct Lad { const float* A; const uint32_t *Bh, *Bl; float* Cf; uint32_t *Ch, *Cl; };
    Lad lads[7];
    lads[0] = {Rf + 7 * SZ, Rh + 7 * SZW, Rl + 7 * SZW, Sf,                  Sh,           Sl};            // S^2
    lads[1] = {Sf,          Sh,           Sl,           Sf + (size_t)1 * SZ, Sh + 1 * SZW, Sl + 1 * SZW};  // S^4
    lads[2] = {Sf + 1 * SZ, Sh + 1 * SZW, Sl + 1 * SZW, Sf + (size_t)2 * SZ, Sh + 2 * SZW, Sl + 2 * SZW};  // S^8
    lads[3] = {Sf + 2 * SZ, Sh + 2 * SZW, Sl + 2 * SZW, Sf + (size_t)3 * SZ, Sh + 3 * SZW, Sl + 3 * SZW};  // S^16
    lads[4] = {Sf + 3 * SZ, Sh + 3 * SZW, Sl + 3 * SZW, Sf + (size_t)4 * SZ, Sh + 4 * SZW, Sl + 4 * SZW};  // S^32
    lads[5] = {Sf + 4 * SZ, Sh + 4 * SZW, Sl + 4 * SZW, Sf + (size_t)5 * SZ, Sh + 5 * SZW, Sl + 5 * SZW};  // S^64
    lads[6] = lads[5];  // unused slot

    // Phase D: carry scan, 7 steps; step i uses S^{2^i} (i=0 -> R^8).
    const float* vin = V0;
    float* vout = V1;
    for (int i = 0; i < 7; i++) {
        const int d = 1 << i;
        const uint32_t* Sph = (i == 0) ? (Rh + (size_t)7 * SZW) : (Sh + (size_t)(i - 1) * SZW);
        const uint32_t* Spl = (i == 0) ? (Rl + (size_t)7 * SZW) : (Sl + (size_t)(i - 1) * SZW);
        const int lext = (i < 6) ? 4 : 0;
        const Lad& L = lads[i];
        hmma_scan_step<<<dim3(8, 32 + lext), 256, SMEM_BYTES>>>(
            vout, vin, Sph, Spl, d, L.A, L.Bh, L.Bl, L.Cf, L.Ch, L.Cl);
        const float* tmp = vin; vin = vout; vout = (float*)tmp;
    }

    // Phase E: batched correction (t = 0..7)
    hmma_pass3_bb<<<dim3(8, 32, Lc), 256, SMEM_BYTES>>>(o, vin, Rh, Rl);
}